// round 2
// baseline (speedup 1.0000x reference)
#include <cuda_runtime.h>

// JacobiKAN layer as a fused GEMM:
//   t = tanh(x);  jac[b,i,d] via Jacobi recurrence (alpha=beta=1)
//   out[b,j] = sum_{i,d} jac[b,i,d] * coef[j,i,d]
// => GEMM with M=B=4096, N=O=512, K=I*8=4096.
// A-tile (jac) is generated on the fly from x inside the K-loop.

#define NI 512          // input size
#define NO 512          // output size
#define DD 8            // order+1
#define BM 128
#define BN 128
#define BK 16           // = 2 input columns * 8 orders
#define NTHREADS 256

__global__ __launch_bounds__(NTHREADS, 1)
void jacobi_kan_gemm(const float* __restrict__ x,
                     const float* __restrict__ coef,
                     float* __restrict__ out)
{
    __shared__ float As[BK][BM];   // [k][m]
    __shared__ float Bs[BK][BN];   // [k][n]

    const int tid  = threadIdx.x;
    const int brow = blockIdx.y * BM;   // batch offset
    const int bcol = blockIdx.x * BN;   // output-feature offset

    // 8x8 micro-tile mapping: 16 x 16 thread grid
    const int tx = tid & 15;   // output-col group
    const int ty = tid >> 4;   // output-row group

    float acc[8][8];
    #pragma unroll
    for (int i = 0; i < 8; ++i)
        #pragma unroll
        for (int j = 0; j < 8; ++j)
            acc[i][j] = 0.0f;

    // A producer mapping: 128 rows x 2 input-columns, one (row, icol) per thread
    const int arow = tid & 127;
    const int ail  = tid >> 7;        // 0 or 1 (which of the 2 input columns)

    // B producer mapping: 128 j-rows x 2 k-halves of 8
    const int bj  = tid & 127;
    const int bkg = tid >> 7;         // 0 or 1

    const float* xrow_ptr = x + (size_t)(brow + arow) * NI;
    const float* crow_ptr = coef + (size_t)(bcol + bj) * (NI * DD);

    for (int kt = 0; kt < NI / 2; ++kt) {
        // ---- produce A tile: compute Jacobi values for x[brow+arow, 2*kt+ail] ----
        {
            float xv = xrow_ptr[kt * 2 + ail];
            float t  = tanhf(xv);
            // alpha=beta=1: K2==0, p1 = 2*t, k1[i]=(2i+2)(2i+1)/(2i(i+2)), k3[i]=(i+1)/(i+2)
            float p0 = 1.0f;
            float p1 = 2.0f * t;
            float p2 = 1.875f      * t * p1 - 0.75f       * p0;
            float p3 = 1.8666667f  * t * p2 - 0.8f        * p1;
            float p4 = 1.875f      * t * p3 - 0.8333333f  * p2;
            float p5 = 1.8857143f  * t * p4 - 0.85714287f * p3;
            float p6 = 1.8958334f  * t * p5 - 0.875f      * p4;
            float p7 = 1.9047619f  * t * p6 - 0.8888889f  * p5;
            const int kb = ail * 8;
            As[kb + 0][arow] = p0;
            As[kb + 1][arow] = p1;
            As[kb + 2][arow] = p2;
            As[kb + 3][arow] = p3;
            As[kb + 4][arow] = p4;
            As[kb + 5][arow] = p5;
            As[kb + 6][arow] = p6;
            As[kb + 7][arow] = p7;
        }
        // ---- produce B tile: coef[j, k0 .. k0+15], transposed into Bs[k][j] ----
        {
            const float4* src = reinterpret_cast<const float4*>(
                crow_ptr + kt * BK + bkg * 8);
            float4 v0 = src[0];
            float4 v1 = src[1];
            const int kb = bkg * 8;
            Bs[kb + 0][bj] = v0.x;
            Bs[kb + 1][bj] = v0.y;
            Bs[kb + 2][bj] = v0.z;
            Bs[kb + 3][bj] = v0.w;
            Bs[kb + 4][bj] = v1.x;
            Bs[kb + 5][bj] = v1.y;
            Bs[kb + 6][bj] = v1.z;
            Bs[kb + 7][bj] = v1.w;
        }
        __syncthreads();

        // ---- compute ----
        #pragma unroll
        for (int k = 0; k < BK; ++k) {
            float a[8], b[8];
            *reinterpret_cast<float4*>(&a[0]) =
                *reinterpret_cast<const float4*>(&As[k][ty * 8]);
            *reinterpret_cast<float4*>(&a[4]) =
                *reinterpret_cast<const float4*>(&As[k][ty * 8 + 4]);
            *reinterpret_cast<float4*>(&b[0]) =
                *reinterpret_cast<const float4*>(&Bs[k][tx * 8]);
            *reinterpret_cast<float4*>(&b[4]) =
                *reinterpret_cast<const float4*>(&Bs[k][tx * 8 + 4]);
            #pragma unroll
            for (int i = 0; i < 8; ++i)
                #pragma unroll
                for (int j = 0; j < 8; ++j)
                    acc[i][j] += a[i] * b[j];
        }
        __syncthreads();
    }

    // ---- epilogue: coalesced float4 stores ----
    #pragma unroll
    for (int i = 0; i < 8; ++i) {
        float* orow = out + (size_t)(brow + ty * 8 + i) * NO + bcol + tx * 8;
        float4 v0 = make_float4(acc[i][0], acc[i][1], acc[i][2], acc[i][3]);
        float4 v1 = make_float4(acc[i][4], acc[i][5], acc[i][6], acc[i][7]);
        reinterpret_cast<float4*>(orow)[0] = v0;
        reinterpret_cast<float4*>(orow)[1] = v1;
    }
}

extern "C" void kernel_launch(void* const* d_in, const int* in_sizes, int n_in,
                              void* d_out, int out_size)
{
    const float* x    = (const float*)d_in[0];   // [B, 512]
    const float* coef = (const float*)d_in[1];   // [512, 512, 8]
    float* out        = (float*)d_out;           // [B, 512]

    const int B = in_sizes[0] / NI;              // 4096

    dim3 grid(NO / BN, B / BM);                  // (4, 32)
    jacobi_kan_gemm<<<grid, NTHREADS>>>(x, coef, out);
}

// round 4
// speedup vs baseline: 3.3395x; 3.3395x over previous
#include <cuda_runtime.h>
#include <cuda_bf16.h>
#include <cstdint>

#define B_SZ 4096
#define NI   512
#define NO   512
#define KK   (NI*8)          // 4096

// ---------------- scratch (device globals; no allocation allowed) ----------
__device__ __nv_bfloat16 g_a_hi[(size_t)B_SZ * KK];   // 32 MB
__device__ __nv_bfloat16 g_a_lo[(size_t)B_SZ * KK];   // 32 MB
__device__ __nv_bfloat16 g_b_hi[(size_t)NO * KK];     //  4 MB
__device__ __nv_bfloat16 g_b_lo[(size_t)NO * KK];     //  4 MB

// ---------------- helpers ---------------------------------------------------
__device__ __forceinline__ uint32_t smem_u32(const void* p) {
    uint32_t a;
    asm("{ .reg .u64 t; cvta.to.shared.u64 t, %1; cvt.u32.u64 %0, t; }"
        : "=r"(a) : "l"(p));
    return a;
}
__device__ __forceinline__ void cp16(uint32_t dst, const void* src) {
    asm volatile("cp.async.cg.shared.global [%0], [%1], 16;"
                 :: "r"(dst), "l"(src));
}
__device__ __forceinline__ void ldsm4(uint32_t* r, uint32_t addr) {
    asm volatile("ldmatrix.sync.aligned.m8n8.x4.shared.b16 {%0,%1,%2,%3}, [%4];"
                 : "=r"(r[0]), "=r"(r[1]), "=r"(r[2]), "=r"(r[3]) : "r"(addr));
}
__device__ __forceinline__ void mma16816(float* d, const uint32_t* a,
                                         uint32_t b0, uint32_t b1) {
    asm volatile(
        "mma.sync.aligned.m16n8k16.row.col.f32.bf16.bf16.f32 "
        "{%0,%1,%2,%3}, {%4,%5,%6,%7}, {%8,%9}, {%0,%1,%2,%3};"
        : "+f"(d[0]), "+f"(d[1]), "+f"(d[2]), "+f"(d[3])
        : "r"(a[0]), "r"(a[1]), "r"(a[2]), "r"(a[3]), "r"(b0), "r"(b1));
}

__device__ __forceinline__ void split8(const float* p, __nv_bfloat16* hi,
                                       __nv_bfloat16* lo) {
    #pragma unroll
    for (int d = 0; d < 8; ++d) {
        hi[d] = __float2bfloat16(p[d]);
        lo[d] = __float2bfloat16(p[d] - __bfloat162float(hi[d]));
    }
}

// ---------------- phase 1: jacobi expansion + coef split --------------------
__global__ __launch_bounds__(256) void jacobi_expand(const float* __restrict__ x) {
    int g = blockIdx.x * 256 + threadIdx.x;   // one (b, i) per thread
    float t = tanhf(x[g]);
    float p[8];
    p[0] = 1.0f;
    p[1] = 2.0f * t;
    p[2] = 1.875f      * t * p[1] - 0.75f       * p[0];
    p[3] = 1.8666667f  * t * p[2] - 0.8f        * p[1];
    p[4] = 1.875f      * t * p[3] - 0.8333333f  * p[2];
    p[5] = 1.8857143f  * t * p[4] - 0.85714287f * p[3];
    p[6] = 1.8958334f  * t * p[5] - 0.875f      * p[4];
    p[7] = 1.9047619f  * t * p[6] - 0.8888889f  * p[5];
    __nv_bfloat16 hi[8], lo[8];
    split8(p, hi, lo);
    *reinterpret_cast<uint4*>(g_a_hi + (size_t)g * 8) = *reinterpret_cast<uint4*>(hi);
    *reinterpret_cast<uint4*>(g_a_lo + (size_t)g * 8) = *reinterpret_cast<uint4*>(lo);
}

__global__ __launch_bounds__(256) void coef_convert(const float* __restrict__ coef) {
    int g = blockIdx.x * 256 + threadIdx.x;   // one (j, i) per thread
    float p[8];
    const float4* s = reinterpret_cast<const float4*>(coef + (size_t)g * 8);
    *reinterpret_cast<float4*>(p)     = s[0];
    *reinterpret_cast<float4*>(p + 4) = s[1];
    __nv_bfloat16 hi[8], lo[8];
    split8(p, hi, lo);
    *reinterpret_cast<uint4*>(g_b_hi + (size_t)g * 8) = *reinterpret_cast<uint4*>(hi);
    *reinterpret_cast<uint4*>(g_b_lo + (size_t)g * 8) = *reinterpret_cast<uint4*>(lo);
}

// ---------------- phase 2: warp-MMA GEMM ------------------------------------
// out[4096,512] = A[4096,4096] @ B[512,4096]^T ; A,B are hi/lo bf16 pairs.
// BM=BN=128, BK=64. Stage = Ah|Al|Bh|Bl, 16KB each -> 64KB. 3 stages.
#define BKH 64
#define STAGE_BYTES 65536
#define NSTAGE 3
#define SMEM_DYN (1024 + NSTAGE * STAGE_BYTES)

// swizzled offset inside a [rows][64 bf16] tile: 128B rows, 16B chunks
__device__ __forceinline__ uint32_t swoff(int row, int chunk) {
    return (uint32_t)(row * 128 + ((chunk ^ (row & 7)) * 16));
}

// load one 128-row x 64-bf16 tile (16KB) with cp.async
__device__ __forceinline__ void load_tile(uint32_t sdst,
                                          const __nv_bfloat16* gsrc, int tid) {
    #pragma unroll
    for (int t = 0; t < 4; ++t) {
        int idx = t * 256 + tid;           // 1024 chunks of 16B
        int row = idx >> 3, ch = idx & 7;
        cp16(sdst + swoff(row, ch),
             (const char*)(gsrc + (size_t)row * KK) + ch * 16);
    }
}

__global__ __launch_bounds__(256, 1)
void kan_gemm(float* __restrict__ out) {
    extern __shared__ char smraw[];
    uint32_t sbase = (smem_u32(smraw) + 1023) & ~1023u;

    const int tid  = threadIdx.x;
    const int lane = tid & 31;
    const int wid  = tid >> 5;
    const int wm   = wid >> 1;          // 0..3  (32-row slice)
    const int wn   = wid & 1;           // 0..1  (64-col slice)
    const int brow = blockIdx.y * 128;
    const int bcol = blockIdx.x * 128;

    const __nv_bfloat16* Ah = g_a_hi + (size_t)brow * KK;
    const __nv_bfloat16* Al = g_a_lo + (size_t)brow * KK;
    const __nv_bfloat16* Bh = g_b_hi + (size_t)bcol * KK;
    const __nv_bfloat16* Bl = g_b_lo + (size_t)bcol * KK;

    float acc[2][8][4];
    #pragma unroll
    for (int i = 0; i < 2; ++i)
        #pragma unroll
        for (int j = 0; j < 8; ++j)
            #pragma unroll
            for (int c = 0; c < 4; ++c) acc[i][j][c] = 0.0f;

    // ldmatrix per-lane row / chunk-half mapping
    const int ar  = lane & 15;           // A: row within m16 tile
    const int ac  = lane >> 4;           // A: k-chunk half (0/1)
    const int br0 = ((lane >> 4) << 3) + (lane & 7);  // B: row within n16 pair
    const int bc  = (lane >> 3) & 1;     // B: k-chunk half (0/1)

    // prologue: stages 0,1
    #pragma unroll
    for (int t = 0; t < NSTAGE - 1; ++t) {
        uint32_t sb = sbase + t * STAGE_BYTES;
        int k0 = t * BKH;
        load_tile(sb,         Ah + k0, tid);
        load_tile(sb + 16384, Al + k0, tid);
        load_tile(sb + 32768, Bh + k0, tid);
        load_tile(sb + 49152, Bl + k0, tid);
        asm volatile("cp.async.commit_group;" ::: "memory");
    }

    const int NIT = KK / BKH;            // 64
    for (int kt = 0; kt < NIT; ++kt) {
        asm volatile("cp.async.wait_group 1;" ::: "memory");
        __syncthreads();

        // prefetch tile kt+2 into stage (kt+2)%3 (consumed at iter kt-1)
        int nk = kt + NSTAGE - 1;
        if (nk < NIT) {
            uint32_t sb = sbase + (nk % NSTAGE) * STAGE_BYTES;
            int k0 = nk * BKH;
            load_tile(sb,         Ah + k0, tid);
            load_tile(sb + 16384, Al + k0, tid);
            load_tile(sb + 32768, Bh + k0, tid);
            load_tile(sb + 49152, Bl + k0, tid);
        }
        asm volatile("cp.async.commit_group;" ::: "memory");

        // compute from stage kt%3
        uint32_t sb  = sbase + (kt % NSTAGE) * STAGE_BYTES;
        uint32_t aBh = sb, aBl = sb + 16384, bBh = sb + 32768, bBl = sb + 49152;

        #pragma unroll
        for (int s = 0; s < 4; ++s) {            // 4 k16 steps in BK=64
            uint32_t ah[2][4], al[2][4];
            #pragma unroll
            for (int mt = 0; mt < 2; ++mt) {
                int row = wm * 32 + mt * 16 + ar;
                uint32_t off = swoff(row, s * 2 + ac);
                ldsm4(ah[mt], aBh + off);
                ldsm4(al[mt], aBl + off);
            }
            uint32_t bh[4][4], bl[4][4];
            #pragma unroll
            for (int p = 0; p < 4; ++p) {
                int row = wn * 64 + p * 16 + br0;
                uint32_t off = swoff(row, s * 2 + bc);
                ldsm4(bh[p], bBh + off);
                ldsm4(bl[p], bBl + off);
            }
            #pragma unroll
            for (int mt = 0; mt < 2; ++mt)
                #pragma unroll
                for (int p = 0; p < 4; ++p) {
                    mma16816(acc[mt][2*p],   ah[mt], bh[p][0], bh[p][1]);
                    mma16816(acc[mt][2*p+1], ah[mt], bh[p][2], bh[p][3]);
                    mma16816(acc[mt][2*p],   al[mt], bh[p][0], bh[p][1]);
                    mma16816(acc[mt][2*p+1], al[mt], bh[p][2], bh[p][3]);
                    mma16816(acc[mt][2*p],   ah[mt], bl[p][0], bl[p][1]);
                    mma16816(acc[mt][2*p+1], ah[mt], bl[p][2], bl[p][3]);
                }
        }
        __syncthreads();
    }

    // epilogue: c-fragment layout -> float2 stores
    const int r0 = brow + wm * 32 + (lane >> 2);
    const int c0 = bcol + wn * 64 + (lane & 3) * 2;
    #pragma unroll
    for (int mt = 0; mt < 2; ++mt) {
        #pragma unroll
        for (int nt = 0; nt < 8; ++nt) {
            float* p = out + (size_t)(r0 + mt * 16) * NO + c0 + nt * 8;
            *reinterpret_cast<float2*>(p) =
                make_float2(acc[mt][nt][0], acc[mt][nt][1]);
            *reinterpret_cast<float2*>(p + 8 * NO) =
                make_float2(acc[mt][nt][2], acc[mt][nt][3]);
        }
    }
}

// ---------------- launcher ---------------------------------------------------
extern "C" void kernel_launch(void* const* d_in, const int* in_sizes, int n_in,
                              void* d_out, int out_size)
{
    const float* x    = (const float*)d_in[0];   // [4096, 512]
    const float* coef = (const float*)d_in[1];   // [512, 512, 8]
    float* out        = (float*)d_out;           // [4096, 512]

    cudaFuncSetAttribute(kan_gemm, cudaFuncAttributeMaxDynamicSharedMemorySize,
                         SMEM_DYN);

    jacobi_expand<<<(B_SZ * NI) / 256, 256>>>(x);
    coef_convert<<<(NO * NI) / 256, 256>>>(coef);

    dim3 grid(NO / 128, B_SZ / 128);             // (4, 32)
    kan_gemm<<<grid, 256, SMEM_DYN>>>(out);
}

// round 5
// speedup vs baseline: 7.4382x; 2.2273x over previous
#include <cuda_runtime.h>
#include <cuda_fp16.h>
#include <cstdint>

#define B_SZ 4096
#define NI   512
#define NO   512
#define KK   (NI*8)          // 4096

// ---------------- scratch (device globals; no allocation allowed) ----------
__device__ __half g_a[(size_t)B_SZ * KK];   // 32 MB
__device__ __half g_b[(size_t)NO * KK];     //  4 MB

// ---------------- helpers ---------------------------------------------------
__device__ __forceinline__ uint32_t smem_u32(const void* p) {
    uint32_t a;
    asm("{ .reg .u64 t; cvta.to.shared.u64 t, %1; cvt.u32.u64 %0, t; }"
        : "=r"(a) : "l"(p));
    return a;
}
__device__ __forceinline__ void cp16(uint32_t dst, const void* src) {
    asm volatile("cp.async.cg.shared.global [%0], [%1], 16;"
                 :: "r"(dst), "l"(src));
}
__device__ __forceinline__ void ldsm4(uint32_t* r, uint32_t addr) {
    asm volatile("ldmatrix.sync.aligned.m8n8.x4.shared.b16 {%0,%1,%2,%3}, [%4];"
                 : "=r"(r[0]), "=r"(r[1]), "=r"(r[2]), "=r"(r[3]) : "r"(addr));
}
__device__ __forceinline__ void mma16816(float* d, const uint32_t* a,
                                         uint32_t b0, uint32_t b1) {
    asm volatile(
        "mma.sync.aligned.m16n8k16.row.col.f32.f16.f16.f32 "
        "{%0,%1,%2,%3}, {%4,%5,%6,%7}, {%8,%9}, {%0,%1,%2,%3};"
        : "+f"(d[0]), "+f"(d[1]), "+f"(d[2]), "+f"(d[3])
        : "r"(a[0]), "r"(a[1]), "r"(a[2]), "r"(a[3]), "r"(b0), "r"(b1));
}

// ---------------- phase 1: jacobi expansion + coef convert ------------------
__global__ __launch_bounds__(256) void jacobi_expand(const float* __restrict__ x) {
    int g = blockIdx.x * 256 + threadIdx.x;   // one (b, i) per thread
    float t = tanhf(x[g]);
    float p[8];
    p[0] = 1.0f;
    p[1] = 2.0f * t;
    p[2] = 1.875f      * t * p[1] - 0.75f       * p[0];
    p[3] = 1.8666667f  * t * p[2] - 0.8f        * p[1];
    p[4] = 1.875f      * t * p[3] - 0.8333333f  * p[2];
    p[5] = 1.8857143f  * t * p[4] - 0.85714287f * p[3];
    p[6] = 1.8958334f  * t * p[5] - 0.875f      * p[4];
    p[7] = 1.9047619f  * t * p[6] - 0.8888889f  * p[5];
    __half h[8];
    #pragma unroll
    for (int d = 0; d < 8; ++d) h[d] = __float2half_rn(p[d]);
    *reinterpret_cast<uint4*>(g_a + (size_t)g * 8) = *reinterpret_cast<uint4*>(h);
}

__global__ __launch_bounds__(256) void coef_convert(const float* __restrict__ coef) {
    int g = blockIdx.x * 256 + threadIdx.x;   // one (j, i) per thread
    float p[8];
    const float4* s = reinterpret_cast<const float4*>(coef + (size_t)g * 8);
    *reinterpret_cast<float4*>(p)     = s[0];
    *reinterpret_cast<float4*>(p + 4) = s[1];
    __half h[8];
    #pragma unroll
    for (int d = 0; d < 8; ++d) h[d] = __float2half_rn(p[d]);
    *reinterpret_cast<uint4*>(g_b + (size_t)g * 8) = *reinterpret_cast<uint4*>(h);
}

// ---------------- phase 2: single-pass fp16 warp-MMA GEMM -------------------
// out[4096,512] = A[4096,4096] @ B[512,4096]^T, fp32 accumulate.
// BM=BN=128, BK=64. Stage = A(16KB) + B(16KB) = 32KB. 4 stages.
#define BKH 64
#define STAGE_BYTES 32768
#define NSTAGE 4
#define SMEM_DYN (1024 + NSTAGE * STAGE_BYTES)

// swizzled offset inside a [rows][64 fp16] tile: 128B rows, 16B chunks
__device__ __forceinline__ uint32_t swoff(int row, int chunk) {
    return (uint32_t)(row * 128 + ((chunk ^ (row & 7)) * 16));
}

// load one 128-row x 64-fp16 tile (16KB) with cp.async
__device__ __forceinline__ void load_tile(uint32_t sdst,
                                          const __half* gsrc, int tid) {
    #pragma unroll
    for (int t = 0; t < 4; ++t) {
        int idx = t * 256 + tid;           // 1024 chunks of 16B
        int row = idx >> 3, ch = idx & 7;
        cp16(sdst + swoff(row, ch),
             (const char*)(gsrc + (size_t)row * KK) + ch * 16);
    }
}

__global__ __launch_bounds__(256, 1)
void kan_gemm(float* __restrict__ out) {
    extern __shared__ char smraw[];
    uint32_t sbase = (smem_u32(smraw) + 1023) & ~1023u;

    const int tid  = threadIdx.x;
    const int lane = tid & 31;
    const int wid  = tid >> 5;
    const int wm   = wid >> 1;          // 0..3  (32-row slice)
    const int wn   = wid & 1;           // 0..1  (64-col slice)
    const int brow = blockIdx.y * 128;
    const int bcol = blockIdx.x * 128;

    const __half* A = g_a + (size_t)brow * KK;
    const __half* B = g_b + (size_t)bcol * KK;

    float acc[2][8][4];
    #pragma unroll
    for (int i = 0; i < 2; ++i)
        #pragma unroll
        for (int j = 0; j < 8; ++j)
            #pragma unroll
            for (int c = 0; c < 4; ++c) acc[i][j][c] = 0.0f;

    // ldmatrix per-lane row / chunk-half mapping (identical to validated R4)
    const int ar  = lane & 15;                        // A row within m16 tile
    const int ac  = lane >> 4;                        // A k-chunk half (0/1)
    const int br0 = ((lane >> 4) << 3) + (lane & 7);  // B row within n16 pair
    const int bc  = (lane >> 3) & 1;                  // B k-chunk half (0/1)

    // prologue: stages 0..2
    #pragma unroll
    for (int t = 0; t < NSTAGE - 1; ++t) {
        uint32_t sb = sbase + t * STAGE_BYTES;
        int k0 = t * BKH;
        load_tile(sb,         A + k0, tid);
        load_tile(sb + 16384, B + k0, tid);
        asm volatile("cp.async.commit_group;" ::: "memory");
    }

    const int NIT = KK / BKH;            // 64
    for (int kt = 0; kt < NIT; ++kt) {
        asm volatile("cp.async.wait_group %0;" :: "n"(NSTAGE - 2) : "memory");
        __syncthreads();

        // prefetch tile kt+3 into stage (kt+3)%4
        int nk = kt + NSTAGE - 1;
        if (nk < NIT) {
            uint32_t sb = sbase + (nk % NSTAGE) * STAGE_BYTES;
            int k0 = nk * BKH;
            load_tile(sb,         A + k0, tid);
            load_tile(sb + 16384, B + k0, tid);
        }
        asm volatile("cp.async.commit_group;" ::: "memory");

        // compute from stage kt%4
        uint32_t sb = sbase + (kt % NSTAGE) * STAGE_BYTES;
        uint32_t aB = sb, bB = sb + 16384;

        #pragma unroll
        for (int s = 0; s < 4; ++s) {            // 4 k16 steps in BK=64
            uint32_t a[2][4];
            #pragma unroll
            for (int mt = 0; mt < 2; ++mt) {
                int row = wm * 32 + mt * 16 + ar;
                ldsm4(a[mt], aB + swoff(row, s * 2 + ac));
            }
            uint32_t b[4][4];
            #pragma unroll
            for (int p = 0; p < 4; ++p) {
                int row = wn * 64 + p * 16 + br0;
                ldsm4(b[p], bB + swoff(row, s * 2 + bc));
            }
            #pragma unroll
            for (int mt = 0; mt < 2; ++mt)
                #pragma unroll
                for (int p = 0; p < 4; ++p) {
                    mma16816(acc[mt][2*p],   a[mt], b[p][0], b[p][1]);
                    mma16816(acc[mt][2*p+1], a[mt], b[p][2], b[p][3]);
                }
        }
        __syncthreads();
    }

    // epilogue: c-fragment layout -> float2 stores
    const int r0 = brow + wm * 32 + (lane >> 2);
    const int c0 = bcol + wn * 64 + (lane & 3) * 2;
    #pragma unroll
    for (int mt = 0; mt < 2; ++mt) {
        #pragma unroll
        for (int nt = 0; nt < 8; ++nt) {
            float* p = out + (size_t)(r0 + mt * 16) * NO + c0 + nt * 8;
            *reinterpret_cast<float2*>(p) =
                make_float2(acc[mt][nt][0], acc[mt][nt][1]);
            *reinterpret_cast<float2*>(p + 8 * NO) =
                make_float2(acc[mt][nt][2], acc[mt][nt][3]);
        }
    }
}

// ---------------- launcher ---------------------------------------------------
extern "C" void kernel_launch(void* const* d_in, const int* in_sizes, int n_in,
                              void* d_out, int out_size)
{
    const float* x    = (const float*)d_in[0];   // [4096, 512]
    const float* coef = (const float*)d_in[1];   // [512, 512, 8]
    float* out        = (float*)d_out;           // [4096, 512]

    cudaFuncSetAttribute(kan_gemm, cudaFuncAttributeMaxDynamicSharedMemorySize,
                         SMEM_DYN);

    jacobi_expand<<<(B_SZ * NI) / 256, 256>>>(x);
    coef_convert<<<(NO * NI) / 256, 256>>>(coef);

    dim3 grid(NO / 128, B_SZ / 128);             // (4, 32)
    kan_gemm<<<grid, 256, SMEM_DYN>>>(out);
}